// round 2
// baseline (speedup 1.0000x reference)
#include <cuda_runtime.h>

#define B_   1024
#define T_   128
#define H_   512
#define NG_  2048

// ---------------- static scratch (no allocations allowed) ----------------
__device__ float g_W1T[1024 * 512];      // [k][i]  (k over [h|c])
__device__ float g_W3T[1024 * 512];      // [k][i]  (k over [z1|z2])
__device__ float g_WgT[1024 * 2048];     // [k][p]  k over [x|h], p = 4*i+q gate-interleaved
__device__ float g_bgp[2048];            // bih+bhh, gate-interleaved
__device__ float g_z2[T_ * B_ * H_];     // precomputed relu(v_t @ W2^T + b2), [t][b][i]
__device__ float g_z1[B_ * H_];
__device__ float g_x [B_ * H_];
__device__ float g_h [2][B_ * H_];       // ping-pong (K3 reads h as GEMM operand while writing h_new)
__device__ float g_c [B_ * H_];

// ---------------- f32x2 packed-FMA helpers (Blackwell FFMA2) ----------------
__device__ __forceinline__ unsigned long long dup2(float a) {
    unsigned long long r;
    asm("mov.b64 %0, {%1, %1};" : "=l"(r) : "f"(a));
    return r;
}
__device__ __forceinline__ void ffma2(unsigned long long& acc,
                                      unsigned long long a, unsigned long long b) {
    asm("fma.rn.f32x2 %0, %1, %2, %0;" : "+l"(acc) : "l"(a), "l"(b));
}
__device__ __forceinline__ float2 unpack2(unsigned long long v) {
    float2 r;
    asm("mov.b64 {%0, %1}, %2;" : "=f"(r.x), "=f"(r.y) : "l"(v));
    return r;
}

// ---------------- prep: transposes, gate interleave, zero state ----------------
__global__ __launch_bounds__(256) void prep_weights(
    const float* __restrict__ W1, const float* __restrict__ W3,
    const float* __restrict__ Wih, const float* __restrict__ Whh,
    const float* __restrict__ bih, const float* __restrict__ bhh)
{
    const int N1 = 1024 * 512;
    const int N2 = N1 + 1024 * 512;
    const int N3 = N2 + 1024 * 2048;
    const int N4 = N3 + 2048;
    const int N5 = N4 + B_ * H_;   // zero g_h[0]
    const int N6 = N5 + B_ * H_;   // zero g_c
    for (int idx = blockIdx.x * blockDim.x + threadIdx.x; idx < N6;
         idx += gridDim.x * blockDim.x) {
        if (idx < N1) {
            int k = idx >> 9, i = idx & 511;
            g_W1T[idx] = W1[i * 1024 + k];
        } else if (idx < N2) {
            int j = idx - N1;
            int k = j >> 9, i = j & 511;
            g_W3T[j] = W3[i * 1024 + k];
        } else if (idx < N3) {
            int j = idx - N2;
            int k = j >> 11, p = j & 2047;
            int i = p >> 2, q = p & 3;
            int r = q * 512 + i;               // PyTorch gate order i,f,g,o
            g_WgT[j] = (k < 512) ? Wih[r * 512 + k] : Whh[r * 512 + (k - 512)];
        } else if (idx < N4) {
            int p = idx - N3;
            int i = p >> 2, q = p & 3;
            int r = q * 512 + i;
            g_bgp[p] = bih[r] + bhh[r];
        } else if (idx < N5) {
            g_h[0][idx - N4] = 0.f;
        } else {
            g_c[idx - N5] = 0.f;
        }
    }
}

// ---------------- prep: z2[t][b][i] = relu(v @ W2^T + b2) for ALL t up front ----------------
__global__ __launch_bounds__(256) void prep_z2(
    const float* __restrict__ sv,   // [B][T][10]
    const float* __restrict__ W2,   // [512][10]
    const float* __restrict__ b2)
{
    __shared__ float W2s[10 * 512];   // transposed: W2s[j][i]
    __shared__ float svs[32 * 10];
    int tid = threadIdx.x;
    for (int idx = tid; idx < 5120; idx += 256) {
        int i = idx / 10, j = idx % 10;
        W2s[j * 512 + i] = W2[idx];
    }
    int u0 = blockIdx.x * 32;   // 32 (b,t) pairs per block, u = b*T + t
    for (int idx = tid; idx < 320; idx += 256) svs[idx] = sv[u0 * 10 + idx];
    __syncthreads();

    int i0 = tid, i1 = tid + 256;
    float bias0 = b2[i0], bias1 = b2[i1];
    for (int p = 0; p < 32; ++p) {
        int u = u0 + p;
        int b = u >> 7, t = u & 127;
        float a0 = bias0, a1 = bias1;
#pragma unroll
        for (int j = 0; j < 10; ++j) {
            float s = svs[p * 10 + j];
            a0 += s * W2s[j * 512 + i0];
            a1 += s * W2s[j * 512 + i1];
        }
        float* dst = g_z2 + (size_t)(t * 1024 + b) * 512;
        dst[i0] = fmaxf(a0, 0.f);
        dst[i1] = fmaxf(a1, 0.f);
    }
}

// ---------------- GEMM 64x64x16, C = relu([A1|A2] @ BT + bias) ----------------
// mode 0: z1 = relu([h_ping | c] @ W1T + b1)      -> g_z1
// mode 1: x  = relu([z1 | z2_t] @ W3T + b3)       -> g_x
__global__ __launch_bounds__(256, 1) void gemm_relu64(
    int mode, int ping, int t, const float* __restrict__ bias)
{
    const float* A1;
    const float* A2;
    const float* BT;
    float* C;
    if (mode == 0) { A1 = g_h[ping]; A2 = g_c;                       BT = g_W1T; C = g_z1; }
    else           { A1 = g_z1;      A2 = g_z2 + (size_t)t * B_ * H_; BT = g_W3T; C = g_x;  }

    __shared__ __align__(16) float As[64 * 20];   // [m][k], pitch 20
    __shared__ __align__(16) float Bs[16 * 64];   // [k][n]

    int tid = threadIdx.x;
    int m0 = blockIdx.x * 64;
    int n0 = blockIdx.y * 64;
    int tm = tid >> 4, tn = tid & 15;

    int am = tid >> 2;          // 0..63
    int ak = (tid & 3) << 2;    // 0,4,8,12
    int bk = tid >> 4;          // 0..15
    int bn = (tid & 15) << 2;   // 0..60

    unsigned long long acc[4][2];
#pragma unroll
    for (int j = 0; j < 4; ++j) { acc[j][0] = 0ULL; acc[j][1] = 0ULL; }

    float4 aR = *(const float4*)(A1 + (m0 + am) * 512 + ak);
    float4 bR = *(const float4*)(BT + bk * 512 + n0 + bn);

    const int KT = 64;   // K = 1024
    for (int kt = 0; kt < KT; ++kt) {
        *(float4*)(&As[am * 20 + ak]) = aR;
        *(float4*)(&Bs[bk * 64 + bn]) = bR;
        __syncthreads();
        if (kt + 1 < KT) {
            int k0n = (kt + 1) * 16;
            const float* Asrc = (k0n < 512) ? A1 : A2;
            int ko = (k0n & 511) + ak;
            aR = *(const float4*)(Asrc + (m0 + am) * 512 + ko);
            bR = *(const float4*)(BT + (k0n + bk) * 512 + n0 + bn);
        }
#pragma unroll
        for (int kk = 0; kk < 16; ++kk) {
            unsigned long long b0 = *(const unsigned long long*)(&Bs[kk * 64 + tn * 4]);
            unsigned long long b1 = *(const unsigned long long*)(&Bs[kk * 64 + tn * 4 + 2]);
#pragma unroll
            for (int j = 0; j < 4; ++j) {
                unsigned long long ad = dup2(As[(tm * 4 + j) * 20 + kk]);
                ffma2(acc[j][0], ad, b0);
                ffma2(acc[j][1], ad, b1);
            }
        }
        __syncthreads();
    }

    float4 bs4 = *(const float4*)(bias + n0 + tn * 4);
#pragma unroll
    for (int j = 0; j < 4; ++j) {
        float2 lo = unpack2(acc[j][0]);
        float2 hi = unpack2(acc[j][1]);
        float4 o;
        o.x = fmaxf(lo.x + bs4.x, 0.f);
        o.y = fmaxf(lo.y + bs4.y, 0.f);
        o.z = fmaxf(hi.x + bs4.z, 0.f);
        o.w = fmaxf(hi.y + bs4.w, 0.f);
        *(float4*)(C + (m0 + tm * 4 + j) * 512 + n0 + tn * 4) = o;
    }
}

// ---------------- GEMM 128x128x16 (gates, gate-interleaved cols) + fused LSTM cell ----------------
__global__ __launch_bounds__(256, 1) void gemm_lstm(
    int ping, int t, float* __restrict__ out)
{
    const float* X   = g_x;
    const float* Hin = g_h[ping];
    float* Hout      = g_h[ping ^ 1];

    __shared__ __align__(16) float As[128 * 20];   // [m][k], pitch 20
    __shared__ __align__(16) float Bs[16 * 128];   // [k][p]

    int tid = threadIdx.x;
    int m0 = blockIdx.x * 128;
    int n0 = blockIdx.y * 128;
    int tm = tid >> 4, tn = tid & 15;

    int am  = tid >> 2;          // 0..63 (+64 second pass)
    int ak  = (tid & 3) << 2;
    int bkk = tid >> 5;          // 0..7  (+8 second pass)
    int bn  = (tid & 31) << 2;   // 0..124

    unsigned long long acc[8][4];
#pragma unroll
    for (int j = 0; j < 8; ++j)
#pragma unroll
        for (int q = 0; q < 4; ++q) acc[j][q] = 0ULL;

    float4 aR0 = *(const float4*)(X + (m0 + am) * 512 + ak);
    float4 aR1 = *(const float4*)(X + (m0 + am + 64) * 512 + ak);
    float4 bR0 = *(const float4*)(g_WgT + (0 + bkk) * 2048 + n0 + bn);
    float4 bR1 = *(const float4*)(g_WgT + (8 + bkk) * 2048 + n0 + bn);

    const int KT = 64;   // K = 1024 over [x|h]
    for (int kt = 0; kt < KT; ++kt) {
        *(float4*)(&As[am * 20 + ak])        = aR0;
        *(float4*)(&As[(am + 64) * 20 + ak]) = aR1;
        *(float4*)(&Bs[bkk * 128 + bn])       = bR0;
        *(float4*)(&Bs[(bkk + 8) * 128 + bn]) = bR1;
        __syncthreads();
        if (kt + 1 < KT) {
            int k0n = (kt + 1) * 16;
            const float* Asrc = (k0n < 512) ? X : Hin;
            int ko = (k0n & 511) + ak;
            aR0 = *(const float4*)(Asrc + (m0 + am) * 512 + ko);
            aR1 = *(const float4*)(Asrc + (m0 + am + 64) * 512 + ko);
            bR0 = *(const float4*)(g_WgT + (k0n + bkk) * 2048 + n0 + bn);
            bR1 = *(const float4*)(g_WgT + (k0n + 8 + bkk) * 2048 + n0 + bn);
        }
#pragma unroll
        for (int kk = 0; kk < 16; ++kk) {
            ulonglong2 bp0 = *(const ulonglong2*)(&Bs[kk * 128 + tn * 8]);
            ulonglong2 bp1 = *(const ulonglong2*)(&Bs[kk * 128 + tn * 8 + 4]);
#pragma unroll
            for (int j = 0; j < 8; ++j) {
                unsigned long long ad = dup2(As[(tm * 8 + j) * 20 + kk]);
                ffma2(acc[j][0], ad, bp0.x);
                ffma2(acc[j][1], ad, bp0.y);
                ffma2(acc[j][2], ad, bp1.x);
                ffma2(acc[j][3], ad, bp1.y);
            }
        }
        __syncthreads();
    }

    // ---- fused LSTM pointwise: thread owns 8 batches x 2 units (all 4 gates local) ----
    int ng = n0 + tn * 8;          // interleaved gate-col base (multiple of 8)
    int i0 = ng >> 2;              // hidden unit index base
    float bb[8];
#pragma unroll
    for (int q = 0; q < 8; ++q) bb[q] = g_bgp[ng + q];

#pragma unroll
    for (int j = 0; j < 8; ++j) {
        int b = m0 + tm * 8 + j;
        float2 p0 = unpack2(acc[j][0]);
        float2 p1 = unpack2(acc[j][1]);
        float2 p2 = unpack2(acc[j][2]);
        float2 p3 = unpack2(acc[j][3]);
        float gv[8] = { p0.x, p0.y, p1.x, p1.y, p2.x, p2.y, p3.x, p3.y };
#pragma unroll
        for (int q = 0; q < 2; ++q) {
            int i = i0 + q;
            float ig = gv[q * 4 + 0] + bb[q * 4 + 0];
            float fg = gv[q * 4 + 1] + bb[q * 4 + 1];
            float gg = gv[q * 4 + 2] + bb[q * 4 + 2];
            float og = gv[q * 4 + 3] + bb[q * 4 + 3];
            float is = 1.f / (1.f + expf(-ig));
            float fs = 1.f / (1.f + expf(-fg));
            float gt = tanhf(gg);
            float os = 1.f / (1.f + expf(-og));
            float cold = g_c[b * 512 + i];
            float cn = fs * cold + is * gt;
            float hn = os * tanhf(cn);
            g_c[b * 512 + i]  = cn;
            Hout[b * 512 + i] = hn;
            out[(size_t)(b * T_ + t) * 512 + i] = hn;
        }
    }
}

// ---------------- launch ----------------
extern "C" void kernel_launch(void* const* d_in, const int* in_sizes, int n_in,
                              void* d_out, int out_size)
{
    const float* sv  = (const float*)d_in[0];
    const float* W1  = (const float*)d_in[1];
    const float* b1  = (const float*)d_in[2];
    const float* W2  = (const float*)d_in[3];
    const float* b2  = (const float*)d_in[4];
    const float* W3  = (const float*)d_in[5];
    const float* b3  = (const float*)d_in[6];
    const float* Wih = (const float*)d_in[7];
    const float* Whh = (const float*)d_in[8];
    const float* bih = (const float*)d_in[9];
    const float* bhh = (const float*)d_in[10];
    float* out = (float*)d_out;

    prep_weights<<<4096, 256>>>(W1, W3, Wih, Whh, bih, bhh);
    prep_z2<<<(B_ * T_) / 32, 256>>>(sv, W2, b2);

    dim3 g1(16, 8);    // 1024/64 x 512/64   = 128 blocks
    dim3 g3(8, 16);    // 1024/128 x 2048/128 = 128 blocks
    for (int t = 0; t < T_; ++t) {
        int ping = t & 1;
        gemm_relu64<<<g1, 256>>>(0, ping, t, b1);
        gemm_relu64<<<g1, 256>>>(1, ping, t, b3);
        gemm_lstm<<<g3, 256>>>(ping, t, out);
    }
}